// round 4
// baseline (speedup 1.0000x reference)
#include <cuda_runtime.h>
#include <cstdint>

#define TSTEPS 4096
#define EMBD 128
#define HIDD 128
#define ZD   512   // 4*HIDD
#define NTOK 16

typedef unsigned long long u64;

// Scratch (static __device__ arrays — no allocation)
__device__ float g_Xp[TSTEPS * ZD];     // 8 MB: per-step input projection + bias
__device__ float g_hs[TSTEPS * HIDD];   // 2 MB: hidden states

// ---------------- packed f32x2 helpers ----------------
__device__ __forceinline__ u64 fma2(u64 a, u64 b, u64 c){
    u64 d; asm("fma.rn.f32x2 %0, %1, %2, %3;" : "=l"(d) : "l"(a), "l"(b), "l"(c)); return d;
}
__device__ __forceinline__ u64 pack2(float lo, float hi){
    u64 d; asm("mov.b64 %0, {%1, %2};" : "=l"(d) : "f"(lo), "f"(hi)); return d;
}
__device__ __forceinline__ float2 unpack2(u64 v){
    float2 r; asm("mov.b64 {%0, %1}, %2;" : "=f"(r.x), "=f"(r.y) : "l"(v)); return r;
}

__device__ __forceinline__ float fast_sigmoid(float x){
    return __fdividef(1.0f, 1.0f + __expf(-x));
}
__device__ __forceinline__ float fast_tanh(float x){
    float xc = fminf(15.0f, fmaxf(-15.0f, x));
    float e = __expf(2.0f * xc);
    return __fdividef(e - 1.0f, e + 1.0f);
}

// =======================================================================
// Kernel 1: Xp[t][j] = (b_ih[j]+b_hh[j]) + dot(w_ih[j,:], emb[x[t]])
// grid 512 blocks x 512 threads, 8 timesteps per block.
// x is read as int32 with a device-side int64/int32 auto-detect:
// if the buffer is little-endian int64 (tokens < 2^31), every odd int32
// word is 0 -> stride 2; otherwise stride 1.
// =======================================================================
__global__ void __launch_bounds__(512) k_input_proj(
    const int* __restrict__ x32, const float* __restrict__ emb,
    const float* __restrict__ w_ih, const float* __restrict__ b_ih,
    const float* __restrict__ b_hh, int vocab)
{
    __shared__ float xe[8][EMBD];
    __shared__ int s_stride;
    const int t0 = blockIdx.x * 8;
    const int tid = threadIdx.x;

    if (tid == 0) {
        int all_zero = 1;
        #pragma unroll
        for (int i = 0; i < 16; i++) all_zero &= (x32[2 * i + 1] == 0);
        s_stride = all_zero ? 2 : 1;   // 2 => int64 source, 1 => int32 source
    }
    __syncthreads();
    const int stride = s_stride;

    // gather 8 embedding rows into smem
    for (int i = tid; i < 8 * EMBD; i += 512) {
        int tt = i / EMBD, k = i % EMBD;
        int tok = x32[(size_t)(t0 + tt) * stride];
        tok = max(0, min(tok, vocab - 1));          // hard bound: never OOB
        xe[tt][k] = emb[(size_t)tok * EMBD + k];
    }
    __syncthreads();

    const int j = tid;  // output gate-row 0..511
    float bias = b_ih[j] + b_hh[j];
    float acc[8];
    #pragma unroll
    for (int tt = 0; tt < 8; tt++) acc[tt] = bias;

    const float4* wrow = reinterpret_cast<const float4*>(w_ih + (size_t)j * EMBD);
    #pragma unroll 8
    for (int k4 = 0; k4 < EMBD / 4; k4++) {
        float4 w = __ldg(&wrow[k4]);
        #pragma unroll
        for (int tt = 0; tt < 8; tt++) {
            const float4 e = *reinterpret_cast<const float4*>(&xe[tt][k4 * 4]);
            acc[tt] += w.x * e.x + w.y * e.y + w.z * e.z + w.w * e.w;
        }
    }
    #pragma unroll
    for (int tt = 0; tt < 8; tt++) g_Xp[(size_t)(t0 + tt) * ZD + j] = acc[tt];
}

// =======================================================================
// Kernel 2: the sequential LSTM recurrence. ONE CTA, 512 threads.
// Thread j owns z[j]: 96 k-columns of W_hh in registers (48 x f32x2),
// 32 k-columns in SMEM. h broadcast from SMEM via 16B loads.
// =======================================================================
#define NREG 96
#define NSMK 32

// dynamic smem layout (bytes)
#define SM_WS 0          // ulonglong2[ (NSMK/4) * 512 ]  = 64 KB
#define SM_H  65536      // float[128]
#define SM_GA 66048      // float[512]
#define SM_TOTAL 68096

__global__ void __launch_bounds__(512, 1) k_lstm(const float* __restrict__ w_hh)
{
    extern __shared__ char smem[];
    ulonglong2* ws2 = reinterpret_cast<ulonglong2*>(smem + SM_WS);
    float* h_s      = reinterpret_cast<float*>(smem + SM_H);
    float* ga_s     = reinterpret_cast<float*>(smem + SM_GA);

    const int j = threadIdx.x;

    // ---- one-time weight staging ----
    u64 wreg[NREG / 2];
    const u64* wrow = reinterpret_cast<const u64*>(w_hh + (size_t)j * HIDD);
    #pragma unroll
    for (int p = 0; p < NREG / 2; p++) wreg[p] = __ldg(&wrow[p]);

    const ulonglong2* wrow2 =
        reinterpret_cast<const ulonglong2*>(w_hh + (size_t)j * HIDD + NREG);
    #pragma unroll
    for (int q = 0; q < NSMK / 4; q++) ws2[q * ZD + j] = __ldg(&wrow2[q]);

    if (j < HIDD) h_s[j] = 0.0f;
    float c = 0.0f;
    __syncthreads();

    const float* xp_ptr = g_Xp + j;
    float xp_next = __ldg(xp_ptr);   // prefetch t=0

    for (int t = 0; t < TSTEPS; t++) {
        float xp = xp_next;
        int tn = (t + 1 < TSTEPS) ? (t + 1) : t;
        xp_next = __ldg(xp_ptr + (size_t)tn * ZD);  // prefetch next step (independent of h)

        const ulonglong2* h2 = reinterpret_cast<const ulonglong2*>(h_s);
        u64 acc0 = pack2(xp, 0.0f);
        u64 acc1 = pack2(0.0f, 0.0f);

        // k = 0..95 : register weights
        #pragma unroll
        for (int q = 0; q < NREG / 4; q++) {
            ulonglong2 hh = h2[q];                 // broadcast LDS.128 (4 h values)
            acc0 = fma2(wreg[2 * q],     hh.x, acc0);
            acc1 = fma2(wreg[2 * q + 1], hh.y, acc1);
        }
        // k = 96..127 : smem weights
        #pragma unroll
        for (int q = 0; q < NSMK / 4; q++) {
            ulonglong2 hh = h2[NREG / 4 + q];
            ulonglong2 ww = ws2[q * ZD + j];       // conflict-free LDS.128
            acc0 = fma2(ww.x, hh.x, acc0);
            acc1 = fma2(ww.y, hh.y, acc1);
        }
        float2 a0 = unpack2(acc0), a1 = unpack2(acc1);
        float z = (a0.x + a0.y) + (a1.x + a1.y);

        // gates: j<128:i  128..255:f  256..383:g(tanh)  384..511:o  (warp-uniform branch)
        float a;
        if (j < 2 * HIDD || j >= 3 * HIDD) a = fast_sigmoid(z);
        else                               a = fast_tanh(z);
        ga_s[j] = a;
        __syncthreads();

        if (j < HIDD) {
            float gi = ga_s[j], gf = ga_s[HIDD + j];
            float gg = ga_s[2 * HIDD + j], go = ga_s[3 * HIDD + j];
            c = gf * c + gi * gg;
            float h = go * fast_tanh(c);
            h_s[j] = h;
            g_hs[(size_t)t * HIDD + j] = h;        // fire-and-forget STG
        }
        __syncthreads();
    }
}

// =======================================================================
// Kernel 3: out[t][n] = b_fc[n] + dot(w_fc[n,:], hs[t])
// grid 128 blocks x 512 threads, 32 timesteps per block
// =======================================================================
__global__ void __launch_bounds__(512) k_out_proj(
    const float* __restrict__ w_fc, const float* __restrict__ b_fc,
    float* __restrict__ out)
{
    __shared__ float wfcT[EMBD][NTOK];   // transposed: conflict-free reads
    __shared__ float hs_s[32][EMBD];

    const int tid = threadIdx.x;
    const int t0 = blockIdx.x * 32;

    for (int i = tid; i < NTOK * EMBD; i += 512) {
        int n = i / EMBD, k = i % EMBD;
        wfcT[k][n] = w_fc[i];
    }
    for (int i = tid; i < 32 * EMBD; i += 512)
        hs_s[i / EMBD][i % EMBD] = g_hs[(size_t)t0 * EMBD + i];
    __syncthreads();

    const int tl = tid / NTOK;
    const int n  = tid % NTOK;
    float acc = b_fc[n];
    #pragma unroll 16
    for (int k = 0; k < EMBD; k++) acc += hs_s[tl][k] * wfcT[k][n];
    out[(size_t)(t0 + tl) * NTOK + n] = acc;
}

// =======================================================================
extern "C" void kernel_launch(void* const* d_in, const int* in_sizes, int n_in,
                              void* d_out, int out_size)
{
    const int* x32       = (const int*)d_in[0];
    const float* emb     = (const float*)d_in[1];
    const float* w_ih    = (const float*)d_in[2];
    const float* w_hh    = (const float*)d_in[3];
    const float* b_ih    = (const float*)d_in[4];
    const float* b_hh    = (const float*)d_in[5];
    const float* w_fc    = (const float*)d_in[6];
    const float* b_fc    = (const float*)d_in[7];
    float* out = (float*)d_out;

    int vocab = in_sizes[1] / EMBD;   // embedding rows actually present

    (void)n_in; (void)out_size;

    cudaFuncSetAttribute(k_lstm, cudaFuncAttributeMaxDynamicSharedMemorySize, SM_TOTAL);

    k_input_proj<<<TSTEPS / 8, 512>>>(x32, emb, w_ih, b_ih, b_hh, vocab);
    k_lstm<<<1, 512, SM_TOTAL>>>(w_hh);
    k_out_proj<<<TSTEPS / 32, 512>>>(w_fc, b_fc, out);
}

// round 5
// speedup vs baseline: 1.6180x; 1.6180x over previous
#include <cuda_runtime.h>
#include <cstdint>

#define TSTEPS 4096
#define EMBD 128
#define HIDD 128
#define ZD   512   // 4*HIDD
#define NTOK 16

typedef unsigned long long u64;

// Scratch (static __device__ arrays — no allocation)
__device__ float g_Xp[TSTEPS * ZD];     // 8 MB: per-step input projection + bias
__device__ float g_hs[TSTEPS * HIDD];   // 2 MB: hidden states

// ---------------- packed f32x2 helpers ----------------
__device__ __forceinline__ u64 fma2(u64 a, u64 b, u64 c){
    u64 d; asm("fma.rn.f32x2 %0, %1, %2, %3;" : "=l"(d) : "l"(a), "l"(b), "l"(c)); return d;
}
__device__ __forceinline__ u64 pack2(float lo, float hi){
    u64 d; asm("mov.b64 %0, {%1, %2};" : "=l"(d) : "f"(lo), "f"(hi)); return d;
}
__device__ __forceinline__ float2 unpack2(u64 v){
    float2 r; asm("mov.b64 {%0, %1}, %2;" : "=f"(r.x), "=f"(r.y) : "l"(v)); return r;
}

__device__ __forceinline__ float fast_sigmoid(float x){
    return __fdividef(1.0f, 1.0f + __expf(-x));
}
__device__ __forceinline__ float fast_tanh(float x){
    float xc = fminf(15.0f, fmaxf(-15.0f, x));
    float e = __expf(2.0f * xc);
    return __fdividef(e - 1.0f, e + 1.0f);
}

__device__ __forceinline__ uint32_t smem_u32(const void* p){
    uint32_t a;
    asm("{ .reg .u64 t; cvta.to.shared.u64 t, %1; cvt.u32.u64 %0, t; }" : "=r"(a) : "l"(p));
    return a;
}

// =======================================================================
// Kernel 1: Xp[t][j] = (b_ih[j]+b_hh[j]) + dot(w_ih[j,:], emb[x[t]])
// x read as int32 with device-side int64/int32 auto-detect.
// =======================================================================
__global__ void __launch_bounds__(512) k_input_proj(
    const int* __restrict__ x32, const float* __restrict__ emb,
    const float* __restrict__ w_ih, const float* __restrict__ b_ih,
    const float* __restrict__ b_hh, int vocab)
{
    __shared__ float xe[8][EMBD];
    __shared__ int s_stride;
    const int t0 = blockIdx.x * 8;
    const int tid = threadIdx.x;

    if (tid == 0) {
        int all_zero = 1;
        #pragma unroll
        for (int i = 0; i < 16; i++) all_zero &= (x32[2 * i + 1] == 0);
        s_stride = all_zero ? 2 : 1;   // 2 => int64 source, 1 => int32 source
    }
    __syncthreads();
    const int stride = s_stride;

    for (int i = tid; i < 8 * EMBD; i += 512) {
        int tt = i / EMBD, k = i % EMBD;
        int tok = x32[(size_t)(t0 + tt) * stride];
        tok = max(0, min(tok, vocab - 1));          // hard bound: never OOB
        xe[tt][k] = emb[(size_t)tok * EMBD + k];
    }
    __syncthreads();

    const int j = tid;
    float bias = b_ih[j] + b_hh[j];
    float acc[8];
    #pragma unroll
    for (int tt = 0; tt < 8; tt++) acc[tt] = bias;

    const float4* wrow = reinterpret_cast<const float4*>(w_ih + (size_t)j * EMBD);
    #pragma unroll 8
    for (int k4 = 0; k4 < EMBD / 4; k4++) {
        float4 w = __ldg(&wrow[k4]);
        #pragma unroll
        for (int tt = 0; tt < 8; tt++) {
            const float4 e = *reinterpret_cast<const float4*>(&xe[tt][k4 * 4]);
            acc[tt] += w.x * e.x + w.y * e.y + w.z * e.z + w.w * e.w;
        }
    }
    #pragma unroll
    for (int tt = 0; tt < 8; tt++) g_Xp[(size_t)(t0 + tt) * ZD + j] = acc[tt];
}

// =======================================================================
// Kernel 2: LSTM recurrence on a 2-CTA cluster (split-M).
// CTA r owns gate rows [256r, 256r+256); each thread holds its full
// 128-wide W_hh row in registers (64 x f32x2). Per step, each CTA sends
// its 256 activations to the peer via st.async (DSMEM + mbarrier
// complete_tx), double-buffered over 2 slots; both CTAs redundantly
// compute the elementwise c/h update.
// =======================================================================
__global__ void __launch_bounds__(256, 1) __cluster_dims__(2, 1, 1)
k_lstm2(const float* __restrict__ w_hh)
{
    __shared__ __align__(16) float ga[2][ZD];   // activation slots (double buffer)
    __shared__ __align__(16) float h_s[HIDD];
    __shared__ __align__(8)  u64   mb[2];       // one mbarrier per slot

    const int j = threadIdx.x;
    uint32_t rank;
    asm("mov.u32 %0, %%cluster_ctarank;" : "=r"(rank));
    const int row = (int)rank * 256 + j;

    // ---- stage full weight row into registers (128 regs) ----
    u64 wreg[64];
    const u64* wrow = reinterpret_cast<const u64*>(w_hh + (size_t)row * HIDD);
    #pragma unroll
    for (int p = 0; p < 64; p++) wreg[p] = __ldg(&wrow[p]);

    // ---- addresses ----
    const uint32_t ga_base = smem_u32(&ga[0][0]);
    const uint32_t mb_base = smem_u32(&mb[0]);
    const uint32_t peer = rank ^ 1u;
    uint32_t r_ga, r_mb;
    asm("mapa.shared::cluster.u32 %0, %1, %2;" : "=r"(r_ga) : "r"(ga_base), "r"(peer));
    asm("mapa.shared::cluster.u32 %0, %1, %2;" : "=r"(r_mb) : "r"(mb_base), "r"(peer));

    if (j == 0) {
        asm volatile("mbarrier.init.shared.b64 [%0], %1;" :: "r"(mb_base),     "r"(1u) : "memory");
        asm volatile("mbarrier.init.shared.b64 [%0], %1;" :: "r"(mb_base + 8), "r"(1u) : "memory");
    }
    if (j < HIDD) h_s[j] = 0.0f;
    float c = 0.0f;
    __syncthreads();
    // mbarriers must be visible cluster-wide before any st.async targets them
    asm volatile("barrier.cluster.arrive.aligned;" ::: "memory");
    asm volatile("barrier.cluster.wait.aligned;"   ::: "memory");

    const float* xp_ptr = g_Xp + row;
    float xp_next = __ldg(xp_ptr);   // prefetch t=0

    const uint32_t my_ga_off = (uint32_t)row * 4u;

    for (int t = 0; t < TSTEPS; t++) {
        const int slot = t & 1;
        const uint32_t ph = (uint32_t)(t >> 1) & 1u;

        // announce expected remote bytes for this slot's phase (256 x 4B)
        if (j == 0) {
            asm volatile("mbarrier.arrive.expect_tx.shared.b64 _, [%0], %1;"
                         :: "r"(mb_base + slot * 8), "r"(1024u) : "memory");
        }

        float xp = xp_next;
        int tn = (t + 1 < TSTEPS) ? (t + 1) : t;
        xp_next = __ldg(xp_ptr + (size_t)tn * ZD);  // next-step prefetch (h-independent)

        // ---- z = xp + dot(wreg, h) : 32 broadcast LDS.128 + 64 FFMA2 ----
        const ulonglong2* h2 = reinterpret_cast<const ulonglong2*>(h_s);
        u64 acc0 = pack2(xp, 0.0f);
        u64 acc1 = pack2(0.0f, 0.0f);
        #pragma unroll
        for (int q = 0; q < 32; q++) {
            ulonglong2 hh = h2[q];
            acc0 = fma2(wreg[2 * q],     hh.x, acc0);
            acc1 = fma2(wreg[2 * q + 1], hh.y, acc1);
        }
        float2 a0 = unpack2(acc0), a1 = unpack2(acc1);
        float z = (a0.x + a0.y) + (a1.x + a1.y);

        // rank0 rows: i,f (sigmoid). rank1: j<128 -> g (tanh), else o (sigmoid).
        float a;
        if (rank == 0)       a = fast_sigmoid(z);
        else if (j < HIDD)   a = fast_tanh(z);
        else                 a = fast_sigmoid(z);

        // ---- send to peer ASAP (remote DSMEM store w/ mbarrier completion) ----
        const uint32_t off = (uint32_t)slot * (ZD * 4u) + my_ga_off;
        asm volatile(
            "st.async.shared::cluster.mbarrier::complete_tx::bytes.b32 [%0], %1, [%2];"
            :: "r"(r_ga + off), "r"(__float_as_uint(a)), "r"(r_mb + slot * 8) : "memory");
        ga[slot][row] = a;      // local copy
        __syncthreads();        // local half of ga[slot] visible

        // ---- combine gates (threads 0..127); only they need the remote data ----
        if (j < HIDD) {
            // wait for peer's 256 activations (phase parity, acquire)
            asm volatile(
                "{\n\t.reg .pred p;\n\t"
                "WL_%=:\n\t"
                "mbarrier.try_wait.parity.acquire.cluster.shared::cta.b64 p, [%0], %1, 0x989680;\n\t"
                "@p bra.uni WD_%=;\n\t"
                "bra.uni WL_%=;\n\t"
                "WD_%=:\n\t}"
                :: "r"(mb_base + slot * 8), "r"(ph) : "memory");

            float gi = ga[slot][j],            gf = ga[slot][HIDD + j];
            float gg = ga[slot][2 * HIDD + j], go = ga[slot][3 * HIDD + j];
            c = gf * c + gi * gg;
            float h = go * fast_tanh(c);
            h_s[j] = h;
            if (rank == 0) g_hs[(size_t)t * HIDD + j] = h;  // single writer
        }
        __syncthreads();        // h_s valid for next step
    }
}

// =======================================================================
// Kernel 3: out[t][n] = b_fc[n] + dot(w_fc[n,:], hs[t])
// =======================================================================
__global__ void __launch_bounds__(512) k_out_proj(
    const float* __restrict__ w_fc, const float* __restrict__ b_fc,
    float* __restrict__ out)
{
    __shared__ float wfcT[EMBD][NTOK];
    __shared__ float hs_s[32][EMBD];

    const int tid = threadIdx.x;
    const int t0 = blockIdx.x * 32;

    for (int i = tid; i < NTOK * EMBD; i += 512) {
        int n = i / EMBD, k = i % EMBD;
        wfcT[k][n] = w_fc[i];
    }
    for (int i = tid; i < 32 * EMBD; i += 512)
        hs_s[i / EMBD][i % EMBD] = g_hs[(size_t)t0 * EMBD + i];
    __syncthreads();

    const int tl = tid / NTOK;
    const int n  = tid % NTOK;
    float acc = b_fc[n];
    #pragma unroll 16
    for (int k = 0; k < EMBD; k++) acc += hs_s[tl][k] * wfcT[k][n];
    out[(size_t)(t0 + tl) * NTOK + n] = acc;
}

// =======================================================================
extern "C" void kernel_launch(void* const* d_in, const int* in_sizes, int n_in,
                              void* d_out, int out_size)
{
    const int* x32       = (const int*)d_in[0];
    const float* emb     = (const float*)d_in[1];
    const float* w_ih    = (const float*)d_in[2];
    const float* w_hh    = (const float*)d_in[3];
    const float* b_ih    = (const float*)d_in[4];
    const float* b_hh    = (const float*)d_in[5];
    const float* w_fc    = (const float*)d_in[6];
    const float* b_fc    = (const float*)d_in[7];
    float* out = (float*)d_out;

    int vocab = in_sizes[1] / EMBD;   // embedding rows actually present

    (void)n_in; (void)out_size;

    k_input_proj<<<TSTEPS / 8, 512>>>(x32, emb, w_ih, b_ih, b_hh, vocab);
    k_lstm2<<<2, 256>>>(w_hh);
    k_out_proj<<<TSTEPS / 32, 512>>>(w_fc, b_fc, out);
}